// round 3
// baseline (speedup 1.0000x reference)
#include <cuda_runtime.h>
#include <cstdint>

#define HEADS 8
#define DIM_HEAD 64
#define NB 4
#define NC 512
#define NL 2048
#define HD (HEADS * DIM_HEAD)   /* 512  */
#define F3 (3 * HD)             /* 1536 */

// Scratch (no allocations allowed -> device globals)
__device__ float g_qkv[(size_t)NB * F3 * NL];   // 48 MB  qkv[b][f][l]  (tf32-rounded, q pre-scaled)
__device__ float g_attn[(size_t)NB * HD * NL];  // 16 MB  attn-out[b][h*64+d][l] (tf32-rounded)
__device__ float g_xt[(size_t)NB * NC * NL];    // 16 MB  x, tf32-rounded
__device__ float g_wq[(size_t)NC * F3];         //        w_qkv, tf32-rounded
__device__ float g_wo[(size_t)HD * NC];         //        w_out, tf32-rounded

__device__ __forceinline__ uint32_t f2tf32(float f) {
    uint32_t u;
    asm("cvt.rna.tf32.f32 %0, %1;" : "=r"(u) : "f"(f));
    return u;
}

__device__ __forceinline__ void mma_tf32(float d[4],
                                         uint32_t a0, uint32_t a1, uint32_t a2, uint32_t a3,
                                         uint32_t b0, uint32_t b1) {
    asm volatile(
        "mma.sync.aligned.m16n8k8.row.col.f32.tf32.tf32.f32 "
        "{%0,%1,%2,%3}, {%4,%5,%6,%7}, {%8,%9}, {%0,%1,%2,%3};"
        : "+f"(d[0]), "+f"(d[1]), "+f"(d[2]), "+f"(d[3])
        : "r"(a0), "r"(a1), "r"(a2), "r"(a3), "r"(b0), "r"(b1));
}

__device__ __forceinline__ void cp16(void* smem, const void* g) {
    uint32_t s = (uint32_t)__cvta_generic_to_shared(smem);
    asm volatile("cp.async.cg.shared.global [%0], [%1], 16;" :: "r"(s), "l"(g));
}
#define CP_COMMIT() asm volatile("cp.async.commit_group;")
#define CP_WAIT0()  asm volatile("cp.async.wait_group 0;")

// ---------------------------------------------------------------------------
// Elementwise tf32 rounding (float4 grid-stride-free, exact-size launch)
// ---------------------------------------------------------------------------
__global__ void cvt_tf32_kernel(const float* __restrict__ in,
                                float* __restrict__ out, int n4)
{
    int i = blockIdx.x * blockDim.x + threadIdx.x;
    if (i < n4) {
        float4 v = ((const float4*)in)[i];
        float4 o;
        o.x = __uint_as_float(f2tf32(v.x));
        o.y = __uint_as_float(f2tf32(v.y));
        o.z = __uint_as_float(f2tf32(v.z));
        o.w = __uint_as_float(f2tf32(v.w));
        ((float4*)out)[i] = o;
    }
}

// ---------------------------------------------------------------------------
// GEMM: Y[b][m][n] = sum_k W[k][m] * X[b][k][n]
// Operands are already tf32-rounded floats; staged as raw bits via cp.async,
// 2-stage double buffer. CTA 128x128, BK=16, 8 warps at 32x64.
// mode 1 (qkv): store tf32-rounded, scale rows m<512 by 0.125.
// mode 0 (out): store fp32 + bias.
// ---------------------------------------------------------------------------
#define GPAD 136
__global__ __launch_bounds__(256) void gemm_tf32_pipe(
    const float* __restrict__ W, const float* __restrict__ X,
    float* __restrict__ Y, const float* __restrict__ bias,
    int M, int N, int K, int mode)
{
    __shared__ uint32_t As[2][16 * GPAD];
    __shared__ uint32_t Bs[2][16 * GPAD];

    const int b  = blockIdx.z;
    const float* Xb = X + (size_t)b * K * N;
    float*       Yb = Y + (size_t)b * M * N;

    const int m0 = blockIdx.y * 128;
    const int n0 = blockIdx.x * 128;
    const int tid  = threadIdx.x;
    const int warp = tid >> 5;
    const int lane = tid & 31;
    const int row  = lane >> 2;
    const int colk = lane & 3;
    const int wm = (warp >> 1) * 32;
    const int wn = (warp & 1) * 64;

    float acc[2][8][4];
#pragma unroll
    for (int i = 0; i < 2; i++)
#pragma unroll
        for (int j = 0; j < 8; j++)
#pragma unroll
            for (int c = 0; c < 4; c++) acc[i][j][c] = 0.f;

    auto load_stage = [&](int st, int k0) {
#pragma unroll
        for (int r = 0; r < 2; r++) {
            int v  = tid + r * 256;        // 0..511
            int kk = v >> 5;               // 0..15
            int ch = (v & 31) * 4;         // word offset 0..124
            cp16(&As[st][kk * GPAD + ch], W  + (size_t)(k0 + kk) * M + m0 + ch);
            cp16(&Bs[st][kk * GPAD + ch], Xb + (size_t)(k0 + kk) * N + n0 + ch);
        }
    };

    const int KT = K / 16;
    load_stage(0, 0);
    CP_COMMIT();

    for (int kt = 0; kt < KT; kt++) {
        CP_WAIT0();
        __syncthreads();
        if (kt + 1 < KT) {
            load_stage((kt + 1) & 1, (kt + 1) * 16);
            CP_COMMIT();
        }
        const uint32_t* A = As[kt & 1];
        const uint32_t* B = Bs[kt & 1];
#pragma unroll
        for (int ks = 0; ks < 2; ks++) {
            const int kb = ks * 8 + colk;
            uint32_t a[2][4];
#pragma unroll
            for (int i = 0; i < 2; i++) {
                a[i][0] = A[kb * GPAD + wm + i * 16 + row];
                a[i][1] = A[kb * GPAD + wm + i * 16 + row + 8];
                a[i][2] = A[(kb + 4) * GPAD + wm + i * 16 + row];
                a[i][3] = A[(kb + 4) * GPAD + wm + i * 16 + row + 8];
            }
#pragma unroll
            for (int j = 0; j < 8; j++) {
                uint32_t b0 = B[kb * GPAD + wn + j * 8 + row];
                uint32_t b1 = B[(kb + 4) * GPAD + wn + j * 8 + row];
#pragma unroll
                for (int i = 0; i < 2; i++)
                    mma_tf32(acc[i][j], a[i][0], a[i][1], a[i][2], a[i][3], b0, b1);
            }
        }
        __syncthreads();
    }

#pragma unroll
    for (int i = 0; i < 2; i++) {
        int m = m0 + wm + i * 16 + row;
        if (mode == 1) {
            float s0 = (m < HD)     ? 0.125f : 1.f;
            float s1 = (m + 8 < HD) ? 0.125f : 1.f;
#pragma unroll
            for (int j = 0; j < 8; j++) {
                int n = n0 + wn + j * 8 + colk * 2;
                Yb[(size_t)m * N + n]           = __uint_as_float(f2tf32(acc[i][j][0] * s0));
                Yb[(size_t)m * N + n + 1]       = __uint_as_float(f2tf32(acc[i][j][1] * s0));
                Yb[(size_t)(m + 8) * N + n]     = __uint_as_float(f2tf32(acc[i][j][2] * s1));
                Yb[(size_t)(m + 8) * N + n + 1] = __uint_as_float(f2tf32(acc[i][j][3] * s1));
            }
        } else {
            float bv0 = bias[m];
            float bv1 = bias[m + 8];
#pragma unroll
            for (int j = 0; j < 8; j++) {
                int n = n0 + wn + j * 8 + colk * 2;
                Yb[(size_t)m * N + n]           = acc[i][j][0] + bv0;
                Yb[(size_t)m * N + n + 1]       = acc[i][j][1] + bv0;
                Yb[(size_t)(m + 8) * N + n]     = acc[i][j][2] + bv1;
                Yb[(size_t)(m + 8) * N + n + 1] = acc[i][j][3] + bv1;
            }
        }
    }
}

// ---------------------------------------------------------------------------
// Flash attention, tf32 mma, cp.async double-buffered K/V.
// One CTA = (b, h, 64-query tile), 128 threads (4 warps, 16 query rows each).
// All inputs already tf32-rounded (q pre-scaled by GEMM epilogue).
// ---------------------------------------------------------------------------
#define QK_PAD 72
#define PV_PAD 68
__global__ __launch_bounds__(128) void attn_tf32(float* __restrict__ out)
{
    extern __shared__ uint32_t sm[];
    uint32_t* Qs = sm;                        // [64][72]
    uint32_t* Ks = Qs + 64 * QK_PAD;          // [2][64][72]
    uint32_t* Vs = Ks + 2 * 64 * QK_PAD;      // [2][64][68]
    uint32_t* Ps = Vs + 2 * 64 * PV_PAD;      // [64][68]

    const int bh = blockIdx.y;
    const int b  = bh >> 3;
    const int h  = bh & 7;
    const int i0 = blockIdx.x * 64;

    const float* qb = g_qkv + (size_t)b * F3 * NL + (size_t)(h * DIM_HEAD) * NL;
    const float* kb = qb + (size_t)HD * NL;
    const float* vb = qb + (size_t)(2 * HD) * NL;

    const int tid  = threadIdx.x;
    const int warp = tid >> 5;
    const int lane = tid & 31;
    const int row  = lane >> 2;
    const int colk = lane & 3;
    const int wi   = warp * 16;

    // Queue Q tile (raw bits): Qs[d][i]
#pragma unroll
    for (int t = 0; t < 8; t++) {
        int v  = tid + t * 128;       // 0..1023
        int d  = v >> 4;
        int ch = (v & 15) * 4;
        cp16(&Qs[d * QK_PAD + ch], qb + (size_t)d * NL + i0 + ch);
    }

    auto load_kv = [&](int st, int j0) {
        uint32_t* K = Ks + st * 64 * QK_PAD;
        uint32_t* V = Vs + st * 64 * PV_PAD;
#pragma unroll
        for (int t = 0; t < 8; t++) {
            int v  = tid + t * 128;
            int d  = v >> 4;
            int ch = (v & 15) * 4;
            cp16(&K[d * QK_PAD + ch], kb + (size_t)d * NL + j0 + ch);
            cp16(&V[d * PV_PAD + ch], vb + (size_t)d * NL + j0 + ch);
        }
    };

    load_kv(0, 0);
    CP_COMMIT();

    float m0r = -1e30f, m1r = -1e30f, l0r = 0.f, l1r = 0.f;
    float o[8][4];
#pragma unroll
    for (int df = 0; df < 8; df++)
#pragma unroll
        for (int c = 0; c < 4; c++) o[df][c] = 0.f;

    const int NT = NL / 64;
    for (int jt = 0; jt < NT; jt++) {
        CP_WAIT0();
        __syncthreads();
        if (jt + 1 < NT) {
            load_kv((jt + 1) & 1, (jt + 1) * 64);
            CP_COMMIT();
        }
        const uint32_t* K = Ks + (jt & 1) * 64 * QK_PAD;
        const uint32_t* V = Vs + (jt & 1) * 64 * PV_PAD;

        // S = Q^T K  (m = i[16], n = j[64], k = d[64])
        float s[8][4];
#pragma unroll
        for (int jf = 0; jf < 8; jf++)
#pragma unroll
            for (int c = 0; c < 4; c++) s[jf][c] = 0.f;

#pragma unroll
        for (int ks = 0; ks < 8; ks++) {
            const int kk = ks * 8 + colk;
            uint32_t a0 = Qs[kk * QK_PAD + wi + row];
            uint32_t a1 = Qs[kk * QK_PAD + wi + row + 8];
            uint32_t a2 = Qs[(kk + 4) * QK_PAD + wi + row];
            uint32_t a3 = Qs[(kk + 4) * QK_PAD + wi + row + 8];
#pragma unroll
            for (int jf = 0; jf < 8; jf++) {
                uint32_t b0 = K[kk * QK_PAD + jf * 8 + row];
                uint32_t b1 = K[(kk + 4) * QK_PAD + jf * 8 + row];
                mma_tf32(s[jf], a0, a1, a2, a3, b0, b1);
            }
        }

        // Online softmax (rows wi+row / wi+row+8; 4-lane row groups)
        float rm0 = -1e30f, rm1 = -1e30f;
#pragma unroll
        for (int jf = 0; jf < 8; jf++) {
            rm0 = fmaxf(rm0, fmaxf(s[jf][0], s[jf][1]));
            rm1 = fmaxf(rm1, fmaxf(s[jf][2], s[jf][3]));
        }
        rm0 = fmaxf(rm0, __shfl_xor_sync(0xffffffffu, rm0, 1, 4));
        rm0 = fmaxf(rm0, __shfl_xor_sync(0xffffffffu, rm0, 2, 4));
        rm1 = fmaxf(rm1, __shfl_xor_sync(0xffffffffu, rm1, 1, 4));
        rm1 = fmaxf(rm1, __shfl_xor_sync(0xffffffffu, rm1, 2, 4));

        float mn0 = fmaxf(m0r, rm0);
        float mn1 = fmaxf(m1r, rm1);
        float corr0 = __expf(m0r - mn0);
        float corr1 = __expf(m1r - mn1);
        m0r = mn0; m1r = mn1;

        float rs0 = 0.f, rs1 = 0.f;
#pragma unroll
        for (int jf = 0; jf < 8; jf++) {
            float p0 = __expf(s[jf][0] - mn0);
            float p1 = __expf(s[jf][1] - mn0);
            float p2 = __expf(s[jf][2] - mn1);
            float p3 = __expf(s[jf][3] - mn1);
            s[jf][0] = p0; s[jf][1] = p1; s[jf][2] = p2; s[jf][3] = p3;
            rs0 += p0 + p1;
            rs1 += p2 + p3;
        }
        rs0 += __shfl_xor_sync(0xffffffffu, rs0, 1, 4);
        rs0 += __shfl_xor_sync(0xffffffffu, rs0, 2, 4);
        rs1 += __shfl_xor_sync(0xffffffffu, rs1, 1, 4);
        rs1 += __shfl_xor_sync(0xffffffffu, rs1, 2, 4);
        l0r = l0r * corr0 + rs0;
        l1r = l1r * corr1 + rs1;

#pragma unroll
        for (int df = 0; df < 8; df++) {
            o[df][0] *= corr0; o[df][1] *= corr0;
            o[df][2] *= corr1; o[df][3] *= corr1;
        }

        // Stage P (tf32) to Ps[i][j] — warp-private rows.
#pragma unroll
        for (int jf = 0; jf < 8; jf++) {
            int jc = jf * 8 + colk * 2;
            Ps[(wi + row) * PV_PAD + jc]         = f2tf32(s[jf][0]);
            Ps[(wi + row) * PV_PAD + jc + 1]     = f2tf32(s[jf][1]);
            Ps[(wi + row + 8) * PV_PAD + jc]     = f2tf32(s[jf][2]);
            Ps[(wi + row + 8) * PV_PAD + jc + 1] = f2tf32(s[jf][3]);
        }
        __syncwarp();

        // O += P V^T  (m = i[16], n = d[64], k = j[64])
#pragma unroll
        for (int ks = 0; ks < 8; ks++) {
            const int kk = ks * 8 + colk;
            uint32_t a0 = Ps[(wi + row) * PV_PAD + kk];
            uint32_t a1 = Ps[(wi + row + 8) * PV_PAD + kk];
            uint32_t a2 = Ps[(wi + row) * PV_PAD + kk + 4];
            uint32_t a3 = Ps[(wi + row + 8) * PV_PAD + kk + 4];
#pragma unroll
            for (int df = 0; df < 8; df++) {
                uint32_t b0 = V[(df * 8 + row) * PV_PAD + kk];
                uint32_t b1 = V[(df * 8 + row) * PV_PAD + kk + 4];
                mma_tf32(o[df], a0, a1, a2, a3, b0, b1);
            }
        }
        __syncwarp();   // Ps reads done before next iteration's overwrite
    }

    // Normalize, round to tf32, stage O[d][i] into Qs (warp-private columns), write out.
    float inv0 = 1.f / l0r;
    float inv1 = 1.f / l1r;
#pragma unroll
    for (int df = 0; df < 8; df++) {
        int d = df * 8 + colk * 2;
        Qs[d * QK_PAD + wi + row]           = f2tf32(o[df][0] * inv0);
        Qs[(d + 1) * QK_PAD + wi + row]     = f2tf32(o[df][1] * inv0);
        Qs[d * QK_PAD + wi + row + 8]       = f2tf32(o[df][2] * inv1);
        Qs[(d + 1) * QK_PAD + wi + row + 8] = f2tf32(o[df][3] * inv1);
    }
    __syncthreads();

    float* ob = out + (size_t)b * HD * NL + (size_t)(h * DIM_HEAD) * NL;
#pragma unroll
    for (int t = 0; t < 8; t++) {
        int v  = tid + t * 128;
        int d  = v >> 4;
        int i4 = (v & 15) * 4;
        float4 o4;
        o4.x = __uint_as_float(Qs[d * QK_PAD + i4 + 0]);
        o4.y = __uint_as_float(Qs[d * QK_PAD + i4 + 1]);
        o4.z = __uint_as_float(Qs[d * QK_PAD + i4 + 2]);
        o4.w = __uint_as_float(Qs[d * QK_PAD + i4 + 3]);
        *(float4*)(ob + (size_t)d * NL + i0 + i4) = o4;
    }
}

// ---------------------------------------------------------------------------
// Launch
// ---------------------------------------------------------------------------
extern "C" void kernel_launch(void* const* d_in, const int* in_sizes, int n_in,
                              void* d_out, int out_size)
{
    const float* x     = (const float*)d_in[0];   // [4, 512, 2048]
    const float* w_qkv = (const float*)d_in[1];   // [512, 1536]
    const float* w_out = (const float*)d_in[2];   // [512, 512]
    const float* b_out = (const float*)d_in[3];   // [512]
    float* y = (float*)d_out;                     // [4, 512, 2048]

    float *qkv, *attn, *xt, *wq, *wo;
    cudaGetSymbolAddress((void**)&qkv,  g_qkv);
    cudaGetSymbolAddress((void**)&attn, g_attn);
    cudaGetSymbolAddress((void**)&xt,   g_xt);
    cudaGetSymbolAddress((void**)&wq,   g_wq);
    cudaGetSymbolAddress((void**)&wo,   g_wo);

    // 0) tf32 pre-rounding
    cvt_tf32_kernel<<<(NB * NC * NL / 4 + 255) / 256, 256>>>(x, xt, NB * NC * NL / 4);
    cvt_tf32_kernel<<<(NC * F3 / 4 + 255) / 256, 256>>>(w_qkv, wq, NC * F3 / 4);
    cvt_tf32_kernel<<<(HD * NC / 4 + 255) / 256, 256>>>(w_out, wo, HD * NC / 4);

    // 1) QKV projection: M=1536, N=2048, K=512 (tf32-rounded out, q scaled)
    {
        dim3 grid(NL / 128, F3 / 128, NB);
        gemm_tf32_pipe<<<grid, 256>>>(wq, xt, qkv, nullptr, F3, NL, NC, 1);
    }

    // 2) Flash attention
    {
        const int smem = (64 * QK_PAD + 2 * 64 * QK_PAD + 2 * 64 * PV_PAD + 64 * PV_PAD)
                         * (int)sizeof(uint32_t);   // 107,520 B
        cudaFuncSetAttribute(attn_tf32,
                             cudaFuncAttributeMaxDynamicSharedMemorySize, smem);
        dim3 grid(NL / 64, NB * HEADS);
        attn_tf32<<<grid, 128, smem>>>(attn);
    }

    // 3) Output projection + bias: M=512, N=2048, K=512
    {
        dim3 grid(NL / 128, HD / 128, NB);
        gemm_tf32_pipe<<<grid, 256>>>(wo, attn, y, b_out, NC, NL, HD, 0);
    }
}

// round 4
// speedup vs baseline: 1.0735x; 1.0735x over previous
#include <cuda_runtime.h>
#include <cstdint>

#define HEADS 8
#define DIM_HEAD 64
#define NB 4
#define NC 512
#define NL 2048
#define HD (HEADS * DIM_HEAD)   /* 512  */
#define F3 (3 * HD)             /* 1536 */

// Scratch (no allocations allowed -> device globals)
__device__ float g_qkv[(size_t)NB * F3 * NL];   // 48 MB  qkv[b][f][l]  (tf32-rounded, q pre-scaled)
__device__ float g_attn[(size_t)NB * HD * NL];  // 16 MB  attn-out[b][h*64+d][l] (tf32-rounded)
__device__ float g_xt[(size_t)NB * NC * NL];    // 16 MB  x, tf32-rounded
__device__ float g_wq[(size_t)NC * F3];         //        w_qkv, tf32-rounded
__device__ float g_wo[(size_t)HD * NC];         //        w_out, tf32-rounded

__device__ __forceinline__ uint32_t f2tf32(float f) {
    uint32_t u;
    asm("cvt.rna.tf32.f32 %0, %1;" : "=r"(u) : "f"(f));
    return u;
}

__device__ __forceinline__ void mma_tf32(float d[4],
                                         uint32_t a0, uint32_t a1, uint32_t a2, uint32_t a3,
                                         uint32_t b0, uint32_t b1) {
    asm volatile(
        "mma.sync.aligned.m16n8k8.row.col.f32.tf32.tf32.f32 "
        "{%0,%1,%2,%3}, {%4,%5,%6,%7}, {%8,%9}, {%0,%1,%2,%3};"
        : "+f"(d[0]), "+f"(d[1]), "+f"(d[2]), "+f"(d[3])
        : "r"(a0), "r"(a1), "r"(a2), "r"(a3), "r"(b0), "r"(b1));
}

__device__ __forceinline__ void cp16(void* smem, const void* g) {
    uint32_t s = (uint32_t)__cvta_generic_to_shared(smem);
    asm volatile("cp.async.cg.shared.global [%0], [%1], 16;" :: "r"(s), "l"(g));
}
#define CP_COMMIT() asm volatile("cp.async.commit_group;")
#define CP_WAIT0()  asm volatile("cp.async.wait_group 0;")

// ---------------------------------------------------------------------------
// Elementwise tf32 rounding
// ---------------------------------------------------------------------------
__global__ void cvt_tf32_kernel(const float* __restrict__ in,
                                float* __restrict__ out, int n4)
{
    int i = blockIdx.x * blockDim.x + threadIdx.x;
    if (i < n4) {
        float4 v = ((const float4*)in)[i];
        float4 o;
        o.x = __uint_as_float(f2tf32(v.x));
        o.y = __uint_as_float(f2tf32(v.y));
        o.z = __uint_as_float(f2tf32(v.z));
        o.w = __uint_as_float(f2tf32(v.w));
        ((float4*)out)[i] = o;
    }
}

// ---------------------------------------------------------------------------
// GEMM: Y[b][m][n] = sum_k W[k][m] * X[b][k][n]
// Pre-rounded tf32 operands staged as raw bits via cp.async, 2-stage pipe.
// CTA 128x128, BK=16, 8 warps at 32x64.
// mode 1 (qkv): store tf32-rounded, scale rows m<512 by 0.125.
// mode 0 (out): store fp32 + bias.
// ---------------------------------------------------------------------------
#define GPAD 136
__global__ __launch_bounds__(256) void gemm_tf32_pipe(
    const float* __restrict__ W, const float* __restrict__ X,
    float* __restrict__ Y, const float* __restrict__ bias,
    int M, int N, int K, int mode)
{
    __shared__ uint32_t As[2][16 * GPAD];
    __shared__ uint32_t Bs[2][16 * GPAD];

    const int b  = blockIdx.z;
    const float* Xb = X + (size_t)b * K * N;
    float*       Yb = Y + (size_t)b * M * N;

    const int m0 = blockIdx.y * 128;
    const int n0 = blockIdx.x * 128;
    const int tid  = threadIdx.x;
    const int warp = tid >> 5;
    const int lane = tid & 31;
    const int row  = lane >> 2;
    const int colk = lane & 3;
    const int wm = (warp >> 1) * 32;
    const int wn = (warp & 1) * 64;

    float acc[2][8][4];
#pragma unroll
    for (int i = 0; i < 2; i++)
#pragma unroll
        for (int j = 0; j < 8; j++)
#pragma unroll
            for (int c = 0; c < 4; c++) acc[i][j][c] = 0.f;

    auto load_stage = [&](int st, int k0) {
#pragma unroll
        for (int r = 0; r < 2; r++) {
            int v  = tid + r * 256;        // 0..511
            int kk = v >> 5;               // 0..15
            int ch = (v & 31) * 4;         // word offset 0..124
            cp16(&As[st][kk * GPAD + ch], W  + (size_t)(k0 + kk) * M + m0 + ch);
            cp16(&Bs[st][kk * GPAD + ch], Xb + (size_t)(k0 + kk) * N + n0 + ch);
        }
    };

    const int KT = K / 16;
    load_stage(0, 0);
    CP_COMMIT();

    for (int kt = 0; kt < KT; kt++) {
        CP_WAIT0();
        __syncthreads();
        if (kt + 1 < KT) {
            load_stage((kt + 1) & 1, (kt + 1) * 16);
            CP_COMMIT();
        }
        const uint32_t* A = As[kt & 1];
        const uint32_t* B = Bs[kt & 1];
#pragma unroll
        for (int ks = 0; ks < 2; ks++) {
            const int kb = ks * 8 + colk;
            uint32_t a[2][4];
#pragma unroll
            for (int i = 0; i < 2; i++) {
                a[i][0] = A[kb * GPAD + wm + i * 16 + row];
                a[i][1] = A[kb * GPAD + wm + i * 16 + row + 8];
                a[i][2] = A[(kb + 4) * GPAD + wm + i * 16 + row];
                a[i][3] = A[(kb + 4) * GPAD + wm + i * 16 + row + 8];
            }
#pragma unroll
            for (int j = 0; j < 8; j++) {
                uint32_t b0 = B[kb * GPAD + wn + j * 8 + row];
                uint32_t b1 = B[(kb + 4) * GPAD + wn + j * 8 + row];
#pragma unroll
                for (int i = 0; i < 2; i++)
                    mma_tf32(acc[i][j], a[i][0], a[i][1], a[i][2], a[i][3], b0, b1);
            }
        }
        __syncthreads();
    }

#pragma unroll
    for (int i = 0; i < 2; i++) {
        int m = m0 + wm + i * 16 + row;
        if (mode == 1) {
            float s0 = (m < HD)     ? 0.125f : 1.f;
            float s1 = (m + 8 < HD) ? 0.125f : 1.f;
#pragma unroll
            for (int j = 0; j < 8; j++) {
                int n = n0 + wn + j * 8 + colk * 2;
                Yb[(size_t)m * N + n]           = __uint_as_float(f2tf32(acc[i][j][0] * s0));
                Yb[(size_t)m * N + n + 1]       = __uint_as_float(f2tf32(acc[i][j][1] * s0));
                Yb[(size_t)(m + 8) * N + n]     = __uint_as_float(f2tf32(acc[i][j][2] * s1));
                Yb[(size_t)(m + 8) * N + n + 1] = __uint_as_float(f2tf32(acc[i][j][3] * s1));
            }
        } else {
            float bv0 = bias[m];
            float bv1 = bias[m + 8];
#pragma unroll
            for (int j = 0; j < 8; j++) {
                int n = n0 + wn + j * 8 + colk * 2;
                Yb[(size_t)m * N + n]           = acc[i][j][0] + bv0;
                Yb[(size_t)m * N + n + 1]       = acc[i][j][1] + bv0;
                Yb[(size_t)(m + 8) * N + n]     = acc[i][j][2] + bv1;
                Yb[(size_t)(m + 8) * N + n + 1] = acc[i][j][3] + bv1;
            }
        }
    }
}

// ---------------------------------------------------------------------------
// Flash attention, tf32 mma. One CTA = (b, h, 128-query tile), 256 threads
// (8 warps, 16 query rows each). cp.async double-buffered 64-key K/V tiles.
// Smem: Qs[64][136], Ks[2][64][72], Vs[2][64][68], Ps[128][68]  (141,312 B).
// Q/P columns are warp-private -> only __syncwarp around P staging.
// ---------------------------------------------------------------------------
#define QPAD 136
#define KPAD 72
#define PV_PAD 68
__global__ __launch_bounds__(256) void attn_tf32(float* __restrict__ out)
{
    extern __shared__ uint32_t sm[];
    uint32_t* Qs = sm;                        // [64][136]
    uint32_t* Ks = Qs + 64 * QPAD;            // [2][64][72]
    uint32_t* Vs = Ks + 2 * 64 * KPAD;        // [2][64][68]
    uint32_t* Ps = Vs + 2 * 64 * PV_PAD;      // [128][68]

    const int bh = blockIdx.y;
    const int b  = bh >> 3;
    const int h  = bh & 7;
    const int i0 = blockIdx.x * 128;

    const float* qb = g_qkv + (size_t)b * F3 * NL + (size_t)(h * DIM_HEAD) * NL;
    const float* kb = qb + (size_t)HD * NL;
    const float* vb = qb + (size_t)(2 * HD) * NL;

    const int tid  = threadIdx.x;
    const int warp = tid >> 5;
    const int lane = tid & 31;
    const int row  = lane >> 2;
    const int colk = lane & 3;
    const int wi   = warp * 16;    // warp's query-row base (0..112)

    // Queue Q tile (raw bits): Qs[d][i], 64 x 128 words
#pragma unroll
    for (int t = 0; t < 8; t++) {
        int v  = tid + t * 256;       // 0..2047
        int d  = v >> 5;              // 0..63
        int ch = (v & 31) * 4;        // 0..124
        cp16(&Qs[d * QPAD + ch], qb + (size_t)d * NL + i0 + ch);
    }

    auto load_kv = [&](int st, int j0) {
        uint32_t* K = Ks + st * 64 * KPAD;
        uint32_t* V = Vs + st * 64 * PV_PAD;
#pragma unroll
        for (int t = 0; t < 4; t++) {
            int v  = tid + t * 256;   // 0..1023
            int d  = v >> 4;          // 0..63
            int ch = (v & 15) * 4;    // 0..60
            cp16(&K[d * KPAD + ch], kb + (size_t)d * NL + j0 + ch);
            cp16(&V[d * PV_PAD + ch], vb + (size_t)d * NL + j0 + ch);
        }
    };

    load_kv(0, 0);
    CP_COMMIT();

    float m0r = -1e30f, m1r = -1e30f, l0r = 0.f, l1r = 0.f;
    float o[8][4];
#pragma unroll
    for (int df = 0; df < 8; df++)
#pragma unroll
        for (int c = 0; c < 4; c++) o[df][c] = 0.f;

    const int NT = NL / 64;
    for (int jt = 0; jt < NT; jt++) {
        CP_WAIT0();
        __syncthreads();
        if (jt + 1 < NT) {
            load_kv((jt + 1) & 1, (jt + 1) * 64);
            CP_COMMIT();
        }
        const uint32_t* K = Ks + (jt & 1) * 64 * KPAD;
        const uint32_t* V = Vs + (jt & 1) * 64 * PV_PAD;

        // S = Q^T K  (m = i[16], n = j[64], k = d[64])
        float s[8][4];
#pragma unroll
        for (int jf = 0; jf < 8; jf++)
#pragma unroll
            for (int c = 0; c < 4; c++) s[jf][c] = 0.f;

#pragma unroll
        for (int ks = 0; ks < 8; ks++) {
            const int kk = ks * 8 + colk;
            uint32_t a0 = Qs[kk * QPAD + wi + row];
            uint32_t a1 = Qs[kk * QPAD + wi + row + 8];
            uint32_t a2 = Qs[(kk + 4) * QPAD + wi + row];
            uint32_t a3 = Qs[(kk + 4) * QPAD + wi + row + 8];
#pragma unroll
            for (int jf = 0; jf < 8; jf++) {
                uint32_t b0 = K[kk * KPAD + jf * 8 + row];
                uint32_t b1 = K[(kk + 4) * KPAD + jf * 8 + row];
                mma_tf32(s[jf], a0, a1, a2, a3, b0, b1);
            }
        }

        // Online softmax (rows wi+row / wi+row+8; 4-lane row groups)
        float rm0 = -1e30f, rm1 = -1e30f;
#pragma unroll
        for (int jf = 0; jf < 8; jf++) {
            rm0 = fmaxf(rm0, fmaxf(s[jf][0], s[jf][1]));
            rm1 = fmaxf(rm1, fmaxf(s[jf][2], s[jf][3]));
        }
        rm0 = fmaxf(rm0, __shfl_xor_sync(0xffffffffu, rm0, 1, 4));
        rm0 = fmaxf(rm0, __shfl_xor_sync(0xffffffffu, rm0, 2, 4));
        rm1 = fmaxf(rm1, __shfl_xor_sync(0xffffffffu, rm1, 1, 4));
        rm1 = fmaxf(rm1, __shfl_xor_sync(0xffffffffu, rm1, 2, 4));

        float mn0 = fmaxf(m0r, rm0);
        float mn1 = fmaxf(m1r, rm1);
        float corr0 = __expf(m0r - mn0);
        float corr1 = __expf(m1r - mn1);
        m0r = mn0; m1r = mn1;

        float rs0 = 0.f, rs1 = 0.f;
#pragma unroll
        for (int jf = 0; jf < 8; jf++) {
            float p0 = __expf(s[jf][0] - mn0);
            float p1 = __expf(s[jf][1] - mn0);
            float p2 = __expf(s[jf][2] - mn1);
            float p3 = __expf(s[jf][3] - mn1);
            s[jf][0] = p0; s[jf][1] = p1; s[jf][2] = p2; s[jf][3] = p3;
            rs0 += p0 + p1;
            rs1 += p2 + p3;
        }
        rs0 += __shfl_xor_sync(0xffffffffu, rs0, 1, 4);
        rs0 += __shfl_xor_sync(0xffffffffu, rs0, 2, 4);
        rs1 += __shfl_xor_sync(0xffffffffu, rs1, 1, 4);
        rs1 += __shfl_xor_sync(0xffffffffu, rs1, 2, 4);
        l0r = l0r * corr0 + rs0;
        l1r = l1r * corr1 + rs1;

#pragma unroll
        for (int df = 0; df < 8; df++) {
            o[df][0] *= corr0; o[df][1] *= corr0;
            o[df][2] *= corr1; o[df][3] *= corr1;
        }

        // Stage P (tf32) to Ps[i][j] — warp-private rows.
#pragma unroll
        for (int jf = 0; jf < 8; jf++) {
            int jc = jf * 8 + colk * 2;
            Ps[(wi + row) * PV_PAD + jc]         = f2tf32(s[jf][0]);
            Ps[(wi + row) * PV_PAD + jc + 1]     = f2tf32(s[jf][1]);
            Ps[(wi + row + 8) * PV_PAD + jc]     = f2tf32(s[jf][2]);
            Ps[(wi + row + 8) * PV_PAD + jc + 1] = f2tf32(s[jf][3]);
        }
        __syncwarp();

        // O += P V^T  (m = i[16], n = d[64], k = j[64])
#pragma unroll
        for (int ks = 0; ks < 8; ks++) {
            const int kk = ks * 8 + colk;
            uint32_t a0 = Ps[(wi + row) * PV_PAD + kk];
            uint32_t a1 = Ps[(wi + row + 8) * PV_PAD + kk];
            uint32_t a2 = Ps[(wi + row) * PV_PAD + kk + 4];
            uint32_t a3 = Ps[(wi + row + 8) * PV_PAD + kk + 4];
#pragma unroll
            for (int df = 0; df < 8; df++) {
                uint32_t b0 = V[(df * 8 + row) * PV_PAD + kk];
                uint32_t b1 = V[(df * 8 + row) * PV_PAD + kk + 4];
                mma_tf32(o[df], a0, a1, a2, a3, b0, b1);
            }
        }
        __syncwarp();   // Ps reads done before next iteration's overwrite
    }

    // Normalize, round to tf32, stage O[d][i] into Qs (warp-private columns), write out.
    float inv0 = 1.f / l0r;
    float inv1 = 1.f / l1r;
#pragma unroll
    for (int df = 0; df < 8; df++) {
        int d = df * 8 + colk * 2;
        Qs[d * QPAD + wi + row]           = f2tf32(o[df][0] * inv0);
        Qs[(d + 1) * QPAD + wi + row]     = f2tf32(o[df][1] * inv0);
        Qs[d * QPAD + wi + row + 8]       = f2tf32(o[df][2] * inv1);
        Qs[(d + 1) * QPAD + wi + row + 8] = f2tf32(o[df][3] * inv1);
    }
    __syncthreads();

    float* ob = out + (size_t)b * HD * NL + (size_t)(h * DIM_HEAD) * NL;
#pragma unroll
    for (int t = 0; t < 8; t++) {
        int v  = tid + t * 256;       // 0..2047
        int d  = v >> 5;              // 0..63
        int i4 = (v & 31) * 4;        // 0..124
        float4 o4;
        o4.x = __uint_as_float(Qs[d * QPAD + i4 + 0]);
        o4.y = __uint_as_float(Qs[d * QPAD + i4 + 1]);
        o4.z = __uint_as_float(Qs[d * QPAD + i4 + 2]);
        o4.w = __uint_as_float(Qs[d * QPAD + i4 + 3]);
        *(float4*)(ob + (size_t)d * NL + i0 + i4) = o4;
    }
}

// ---------------------------------------------------------------------------
// Launch
// ---------------------------------------------------------------------------
extern "C" void kernel_launch(void* const* d_in, const int* in_sizes, int n_in,
                              void* d_out, int out_size)
{
    const float* x     = (const float*)d_in[0];   // [4, 512, 2048]
    const float* w_qkv = (const float*)d_in[1];   // [512, 1536]
    const float* w_out = (const float*)d_in[2];   // [512, 512]
    const float* b_out = (const float*)d_in[3];   // [512]
    float* y = (float*)d_out;                     // [4, 512, 2048]

    float *qkv, *attn, *xt, *wq, *wo;
    cudaGetSymbolAddress((void**)&qkv,  g_qkv);
    cudaGetSymbolAddress((void**)&attn, g_attn);
    cudaGetSymbolAddress((void**)&xt,   g_xt);
    cudaGetSymbolAddress((void**)&wq,   g_wq);
    cudaGetSymbolAddress((void**)&wo,   g_wo);

    // 0) tf32 pre-rounding
    cvt_tf32_kernel<<<(NB * NC * NL / 4 + 255) / 256, 256>>>(x, xt, NB * NC * NL / 4);
    cvt_tf32_kernel<<<(NC * F3 / 4 + 255) / 256, 256>>>(w_qkv, wq, NC * F3 / 4);
    cvt_tf32_kernel<<<(HD * NC / 4 + 255) / 256, 256>>>(w_out, wo, HD * NC / 4);

    // 1) QKV projection: M=1536, N=2048, K=512 (tf32-rounded out, q scaled)
    {
        dim3 grid(NL / 128, F3 / 128, NB);
        gemm_tf32_pipe<<<grid, 256>>>(wq, xt, qkv, nullptr, F3, NL, NC, 1);
    }

    // 2) Flash attention (128-query tiles)
    {
        const int smem = (64 * QPAD + 2 * 64 * KPAD + 2 * 64 * PV_PAD + 128 * PV_PAD)
                         * (int)sizeof(uint32_t);   // 141,312 B
        cudaFuncSetAttribute(attn_tf32,
                             cudaFuncAttributeMaxDynamicSharedMemorySize, smem);
        dim3 grid(NL / 128, NB * HEADS);
        attn_tf32<<<grid, 256, smem>>>(attn);
    }

    // 3) Output projection + bias: M=512, N=2048, K=512
    {
        dim3 grid(NL / 128, HD / 128, NB);
        gemm_tf32_pipe<<<grid, 256>>>(wo, attn, y, b_out, NC, NL, HD, 0);
    }
}

// round 5
// speedup vs baseline: 1.1749x; 1.0945x over previous
#include <cuda_runtime.h>
#include <cstdint>

#define HEADS 8
#define DIM_HEAD 64
#define NB 4
#define NC 512
#define NL 2048
#define HD (HEADS * DIM_HEAD)   /* 512  */
#define F3 (3 * HD)             /* 1536 */

// Scratch (no allocations allowed -> device globals)
__device__ float g_qkv[(size_t)NB * F3 * NL];   // qkv[b][f][l] (tf32-rounded; q pre-scaled by 0.125*log2e)
__device__ float g_attn[(size_t)NB * HD * NL];  // attn-out[b][h*64+d][l] (tf32-rounded)
__device__ float g_xt[(size_t)NB * NC * NL];    // x, tf32-rounded
__device__ float g_wq[(size_t)NC * F3];
__device__ float g_wo[(size_t)HD * NC];

__device__ __forceinline__ uint32_t f2tf32(float f) {
    uint32_t u;
    asm("cvt.rna.tf32.f32 %0, %1;" : "=r"(u) : "f"(f));
    return u;
}

__device__ __forceinline__ void mma_tf32(float d[4],
                                         uint32_t a0, uint32_t a1, uint32_t a2, uint32_t a3,
                                         uint32_t b0, uint32_t b1) {
    asm volatile(
        "mma.sync.aligned.m16n8k8.row.col.f32.tf32.tf32.f32 "
        "{%0,%1,%2,%3}, {%4,%5,%6,%7}, {%8,%9}, {%0,%1,%2,%3};"
        : "+f"(d[0]), "+f"(d[1]), "+f"(d[2]), "+f"(d[3])
        : "r"(a0), "r"(a1), "r"(a2), "r"(a3), "r"(b0), "r"(b1));
}

__device__ __forceinline__ void cp16(void* smem, const void* g) {
    uint32_t s = (uint32_t)__cvta_generic_to_shared(smem);
    asm volatile("cp.async.cg.shared.global [%0], [%1], 16;" :: "r"(s), "l"(g));
}
#define CP_COMMIT() asm volatile("cp.async.commit_group;")
#define CP_WAIT(n)  asm volatile("cp.async.wait_group %0;" :: "n"(n))

// ---------------------------------------------------------------------------
// Elementwise tf32 rounding
// ---------------------------------------------------------------------------
__global__ void cvt_tf32_kernel(const float* __restrict__ in,
                                float* __restrict__ out, int n4)
{
    int i = blockIdx.x * blockDim.x + threadIdx.x;
    if (i < n4) {
        float4 v = ((const float4*)in)[i];
        float4 o;
        o.x = __uint_as_float(f2tf32(v.x));
        o.y = __uint_as_float(f2tf32(v.y));
        o.z = __uint_as_float(f2tf32(v.z));
        o.w = __uint_as_float(f2tf32(v.w));
        ((float4*)out)[i] = o;
    }
}

// ---------------------------------------------------------------------------
// GEMM: Y[b][m][n] = sum_k W[k][m] * X[b][k][n]
// Pre-rounded tf32 operands, cp.async 3-stage pipeline, 1 barrier/iter.
// CTA 128x128, BK=16, 8 warps at 32x64.
// mode 1 (qkv): store tf32-rounded; rows m<512 (= q) scaled by 0.125*log2e.
// mode 0 (out): store fp32 + bias.
// ---------------------------------------------------------------------------
#define GPAD 136
#define QSCALE (0.125f * 1.4426950408889634f)
__global__ __launch_bounds__(256) void gemm_tf32_pipe(
    const float* __restrict__ W, const float* __restrict__ X,
    float* __restrict__ Y, const float* __restrict__ bias,
    int M, int N, int K, int mode)
{
    __shared__ uint32_t As[3][16 * GPAD];
    __shared__ uint32_t Bs[3][16 * GPAD];

    const int b  = blockIdx.z;
    const float* Xb = X + (size_t)b * K * N;
    float*       Yb = Y + (size_t)b * M * N;

    const int m0 = blockIdx.y * 128;
    const int n0 = blockIdx.x * 128;
    const int tid  = threadIdx.x;
    const int warp = tid >> 5;
    const int lane = tid & 31;
    const int row  = lane >> 2;
    const int colk = lane & 3;
    const int wm = (warp >> 1) * 32;
    const int wn = (warp & 1) * 64;

    float acc[2][8][4];
#pragma unroll
    for (int i = 0; i < 2; i++)
#pragma unroll
        for (int j = 0; j < 8; j++)
#pragma unroll
            for (int c = 0; c < 4; c++) acc[i][j][c] = 0.f;

    auto load_stage = [&](int st, int k0) {
#pragma unroll
        for (int r = 0; r < 2; r++) {
            int v  = tid + r * 256;        // 0..511
            int kk = v >> 5;               // 0..15
            int ch = (v & 31) * 4;         // word offset 0..124
            cp16(&As[st][kk * GPAD + ch], W  + (size_t)(k0 + kk) * M + m0 + ch);
            cp16(&Bs[st][kk * GPAD + ch], Xb + (size_t)(k0 + kk) * N + n0 + ch);
        }
    };

    const int KT = K / 16;
    load_stage(0, 0);  CP_COMMIT();
    load_stage(1, 16); CP_COMMIT();

    int st = 0;
    for (int kt = 0; kt < KT; kt++) {
        CP_WAIT(1);          // stage kt arrived (FIFO)
        __syncthreads();     // visibility + stage (kt+2)%3 free
        if (kt + 2 < KT) {
            load_stage((kt + 2) % 3, (kt + 2) * 16);
            CP_COMMIT();
        }
        const uint32_t* A = As[st];
        const uint32_t* B = Bs[st];
        st = (st + 1 == 3) ? 0 : st + 1;
#pragma unroll
        for (int ks = 0; ks < 2; ks++) {
            const int kb = ks * 8 + colk;
            uint32_t a[2][4];
#pragma unroll
            for (int i = 0; i < 2; i++) {
                a[i][0] = A[kb * GPAD + wm + i * 16 + row];
                a[i][1] = A[kb * GPAD + wm + i * 16 + row + 8];
                a[i][2] = A[(kb + 4) * GPAD + wm + i * 16 + row];
                a[i][3] = A[(kb + 4) * GPAD + wm + i * 16 + row + 8];
            }
#pragma unroll
            for (int j = 0; j < 8; j++) {
                uint32_t b0 = B[kb * GPAD + wn + j * 8 + row];
                uint32_t b1 = B[(kb + 4) * GPAD + wn + j * 8 + row];
#pragma unroll
                for (int i = 0; i < 2; i++)
                    mma_tf32(acc[i][j], a[i][0], a[i][1], a[i][2], a[i][3], b0, b1);
            }
        }
        __syncthreads();     // all warps done with stage kt before next overwrite window
    }

#pragma unroll
    for (int i = 0; i < 2; i++) {
        int m = m0 + wm + i * 16 + row;
        if (mode == 1) {
            float s0 = (m < HD)     ? QSCALE : 1.f;
            float s1 = (m + 8 < HD) ? QSCALE : 1.f;
#pragma unroll
            for (int j = 0; j < 8; j++) {
                int n = n0 + wn + j * 8 + colk * 2;
                Yb[(size_t)m * N + n]           = __uint_as_float(f2tf32(acc[i][j][0] * s0));
                Yb[(size_t)m * N + n + 1]       = __uint_as_float(f2tf32(acc[i][j][1] * s0));
                Yb[(size_t)(m + 8) * N + n]     = __uint_as_float(f2tf32(acc[i][j][2] * s1));
                Yb[(size_t)(m + 8) * N + n + 1] = __uint_as_float(f2tf32(acc[i][j][3] * s1));
            }
        } else {
            float bv0 = bias[m];
            float bv1 = bias[m + 8];
#pragma unroll
            for (int j = 0; j < 8; j++) {
                int n = n0 + wn + j * 8 + colk * 2;
                Yb[(size_t)m * N + n]           = acc[i][j][0] + bv0;
                Yb[(size_t)m * N + n + 1]       = acc[i][j][1] + bv0;
                Yb[(size_t)(m + 8) * N + n]     = acc[i][j][2] + bv1;
                Yb[(size_t)(m + 8) * N + n + 1] = acc[i][j][3] + bv1;
            }
        }
    }
}

// ---------------------------------------------------------------------------
// Flash attention, tf32 mma. One CTA = (b, h, 128-query tile), 256 threads
// (8 warps, 16 query rows each). SINGLE K/V buffer with split cp.async
// commit groups: K_{t+1} loads during PV_t, V_t loads during QK_t+softmax_t.
// Smem: Qs[64][136], Ks[64][72], Vs[64][68], Ps[128][68] = 105,472 B
// -> 2 CTAs/SM = 16 warps/SM.  Softmax in exp2 domain (Q pre-scaled).
// ---------------------------------------------------------------------------
#define QPAD 136
#define KPAD 72
#define PV_PAD 68
__global__ __launch_bounds__(256, 2) void attn_tf32(float* __restrict__ out)
{
    extern __shared__ uint32_t sm[];
    uint32_t* Qs = sm;                        // [64][136]
    uint32_t* Ks = Qs + 64 * QPAD;            // [64][72]
    uint32_t* Vs = Ks + 64 * KPAD;            // [64][68]
    uint32_t* Ps = Vs + 64 * PV_PAD;          // [128][68]

    const int bh = blockIdx.y;
    const int b  = bh >> 3;
    const int h  = bh & 7;
    const int i0 = blockIdx.x * 128;

    const float* qb = g_qkv + (size_t)b * F3 * NL + (size_t)(h * DIM_HEAD) * NL;
    const float* kb = qb + (size_t)HD * NL;
    const float* vb = qb + (size_t)(2 * HD) * NL;

    const int tid  = threadIdx.x;
    const int warp = tid >> 5;
    const int lane = tid & 31;
    const int row  = lane >> 2;
    const int colk = lane & 3;
    const int wi   = warp * 16;    // warp's query-row base (0..112)

    auto load_k = [&](int j0) {
#pragma unroll
        for (int t = 0; t < 4; t++) {
            int v  = tid + t * 256;   // 0..1023
            int d  = v >> 4;          // 0..63
            int ch = (v & 15) * 4;    // 0..60
            cp16(&Ks[d * KPAD + ch], kb + (size_t)d * NL + j0 + ch);
        }
    };
    auto load_v = [&](int j0) {
#pragma unroll
        for (int t = 0; t < 4; t++) {
            int v  = tid + t * 256;
            int d  = v >> 4;
            int ch = (v & 15) * 4;
            cp16(&Vs[d * PV_PAD + ch], vb + (size_t)d * NL + j0 + ch);
        }
    };

    // Prologue: queue Q (group 0) and K_0 (group 1).
#pragma unroll
    for (int t = 0; t < 8; t++) {
        int v  = tid + t * 256;       // 0..2047
        int d  = v >> 5;              // 0..63
        int ch = (v & 31) * 4;        // 0..124
        cp16(&Qs[d * QPAD + ch], qb + (size_t)d * NL + i0 + ch);
    }
    CP_COMMIT();
    load_k(0);
    CP_COMMIT();

    float m0r = -1e30f, m1r = -1e30f, l0r = 0.f, l1r = 0.f;
    float o[8][4];
#pragma unroll
    for (int df = 0; df < 8; df++)
#pragma unroll
        for (int c = 0; c < 4; c++) o[df][c] = 0.f;

    const int NT = NL / 64;
    for (int jt = 0; jt < NT; jt++) {
        const int j0 = jt * 64;

        __syncthreads();              // all warps done reading V_{t-1}
        load_v(j0);                   // V_t loads under QK_t + softmax_t
        CP_COMMIT();
        CP_WAIT(1);                   // K_t (and Q) complete; V_t may be in flight
        __syncthreads();              // K_t visible to all warps

        // S = Q^T K  (m = i[16], n = j[64], k = d[64])
        float s[8][4];
#pragma unroll
        for (int jf = 0; jf < 8; jf++)
#pragma unroll
            for (int c = 0; c < 4; c++) s[jf][c] = 0.f;

#pragma unroll
        for (int ks = 0; ks < 8; ks++) {
            const int kk = ks * 8 + colk;
            uint32_t a0 = Qs[kk * QPAD + wi + row];
            uint32_t a1 = Qs[kk * QPAD + wi + row + 8];
            uint32_t a2 = Qs[(kk + 4) * QPAD + wi + row];
            uint32_t a3 = Qs[(kk + 4) * QPAD + wi + row + 8];
#pragma unroll
            for (int jf = 0; jf < 8; jf++) {
                uint32_t b0 = Ks[kk * KPAD + jf * 8 + row];
                uint32_t b1 = Ks[(kk + 4) * KPAD + jf * 8 + row];
                mma_tf32(s[jf], a0, a1, a2, a3, b0, b1);
            }
        }

        // Online softmax in exp2 domain (Q pre-scaled by 0.125*log2e).
        float rm0 = -1e30f, rm1 = -1e30f;
#pragma unroll
        for (int jf = 0; jf < 8; jf++) {
            rm0 = fmaxf(rm0, fmaxf(s[jf][0], s[jf][1]));
            rm1 = fmaxf(rm1, fmaxf(s[jf][2], s[jf][3]));
        }
        rm0 = fmaxf(rm0, __shfl_xor_sync(0xffffffffu, rm0, 1, 4));
        rm0 = fmaxf(rm0, __shfl_xor_sync(0xffffffffu, rm0, 2, 4));
        rm1 = fmaxf(rm1, __shfl_xor_sync(0xffffffffu, rm1, 1, 4));
        rm1 = fmaxf(rm1, __shfl_xor_sync(0xffffffffu, rm1, 2, 4));

        float mn0 = fmaxf(m0r, rm0);
        float mn1 = fmaxf(m1r, rm1);
        float corr0 = exp2f(m0r - mn0);
        float corr1 = exp2f(m1r - mn1);
        m0r = mn0; m1r = mn1;

        float rs0 = 0.f, rs1 = 0.f;
#pragma unroll
        for (int jf = 0; jf < 8; jf++) {
            float p0 = exp2f(s[jf][0] - mn0);
            float p1 = exp2f(s[jf][1] - mn0);
            float p2 = exp2f(s[jf][2] - mn1);
            float p3 = exp2f(s[jf][3] - mn1);
            s[jf][0] = p0; s[jf][1] = p1; s[jf][2] = p2; s[jf][3] = p3;
            rs0 += p0 + p1;
            rs1 += p2 + p3;
        }
        rs0 += __shfl_xor_sync(0xffffffffu, rs0, 1, 4);
        rs0 += __shfl_xor_sync(0xffffffffu, rs0, 2, 4);
        rs1 += __shfl_xor_sync(0xffffffffu, rs1, 1, 4);
        rs1 += __shfl_xor_sync(0xffffffffu, rs1, 2, 4);
        l0r = l0r * corr0 + rs0;
        l1r = l1r * corr1 + rs1;

#pragma unroll
        for (int df = 0; df < 8; df++) {
            o[df][0] *= corr0; o[df][1] *= corr0;
            o[df][2] *= corr1; o[df][3] *= corr1;
        }

        // Stage P (tf32) to Ps[i][j] — warp-private rows.
#pragma unroll
        for (int jf = 0; jf < 8; jf++) {
            int jc = jf * 8 + colk * 2;
            Ps[(wi + row) * PV_PAD + jc]         = f2tf32(s[jf][0]);
            Ps[(wi + row) * PV_PAD + jc + 1]     = f2tf32(s[jf][1]);
            Ps[(wi + row + 8) * PV_PAD + jc]     = f2tf32(s[jf][2]);
            Ps[(wi + row + 8) * PV_PAD + jc + 1] = f2tf32(s[jf][3]);
        }
        __syncwarp();

        __syncthreads();              // all warps done reading K_t -> K buffer free
        if (jt + 1 < NT) {
            load_k(j0 + 64);          // K_{t+1} loads under PV_t
            CP_COMMIT();
        }
        CP_WAIT(1);                   // V_t complete (FIFO: older than K_{t+1})
        __syncthreads();              // V_t visible to all warps

        // O += P V^T  (m = i[16], n = d[64], k = j[64])
#pragma unroll
        for (int ks = 0; ks < 8; ks++) {
            const int kk = ks * 8 + colk;
            uint32_t a0 = Ps[(wi + row) * PV_PAD + kk];
            uint32_t a1 = Ps[(wi + row + 8) * PV_PAD + kk];
            uint32_t a2 = Ps[(wi + row) * PV_PAD + kk + 4];
            uint32_t a3 = Ps[(wi + row + 8) * PV_PAD + kk + 4];
#pragma unroll
            for (int df = 0; df < 8; df++) {
                uint32_t b0 = Vs[(df * 8 + row) * PV_PAD + kk];
                uint32_t b1 = Vs[(df * 8 + row) * PV_PAD + kk + 4];
                mma_tf32(o[df], a0, a1, a2, a3, b0, b1);
            }
        }
    }

    // Normalize, round to tf32, stage O[d][i] into Qs (warp-private columns), write out.
    float inv0 = 1.f / l0r;
    float inv1 = 1.f / l1r;
    __syncthreads();
#pragma unroll
    for (int df = 0; df < 8; df++) {
        int d = df * 8 + colk * 2;
        Qs[d * QPAD + wi + row]           = f2tf32(o[df][0] * inv0);
        Qs[(d + 1) * QPAD + wi + row]     = f2tf32(o[df][1] * inv0);
        Qs[d * QPAD + wi + row + 8]       = f2tf32(o[df][2] * inv1);
        Qs[(d + 1) * QPAD + wi + row + 8] = f2tf32(o[df][3] * inv1);
    }
    __syncthreads();

    float* ob = out + (size_t)b * HD * NL + (size_t)(h * DIM_HEAD) * NL;
#pragma unroll
    for (int t = 0; t < 8; t++) {
        int v  = tid + t * 256;       // 0..2047
        int d  = v >> 5;              // 0..63
        int i4 = (v & 31) * 4;        // 0..124
        float4 o4;
        o4.x = __uint_as_float(Qs[d * QPAD + i4 + 0]);
        o4.y = __uint_as_float(Qs[d * QPAD + i4 + 1]);
        o4.z = __uint_as_float(Qs[d * QPAD + i4 + 2]);
        o4.w = __uint_as_float(Qs[d * QPAD + i4 + 3]);
        *(float4*)(ob + (size_t)d * NL + i0 + i4) = o4;
    }
}

// ---------------------------------------------------------------------------
// Launch
// ---------------------------------------------------------------------------
extern "C" void kernel_launch(void* const* d_in, const int* in_sizes, int n_in,
                              void* d_out, int out_size)
{
    const float* x     = (const float*)d_in[0];   // [4, 512, 2048]
    const float* w_qkv = (const float*)d_in[1];   // [512, 1536]
    const float* w_out = (const float*)d_in[2];   // [512, 512]
    const float* b_out = (const float*)d_in[3];   // [512]
    float* y = (float*)d_out;                     // [4, 512, 2048]

    float *qkv, *attn, *xt, *wq, *wo;
    cudaGetSymbolAddress((void**)&qkv,  g_qkv);
    cudaGetSymbolAddress((void**)&attn, g_attn);
    cudaGetSymbolAddress((void**)&xt,   g_xt);
    cudaGetSymbolAddress((void**)&wq,   g_wq);
    cudaGetSymbolAddress((void**)&wo,   g_wo);

    // 0) tf32 pre-rounding
    cvt_tf32_kernel<<<(NB * NC * NL / 4 + 255) / 256, 256>>>(x, xt, NB * NC * NL / 4);
    cvt_tf32_kernel<<<(NC * F3 / 4 + 255) / 256, 256>>>(w_qkv, wq, NC * F3 / 4);
    cvt_tf32_kernel<<<(HD * NC / 4 + 255) / 256, 256>>>(w_out, wo, HD * NC / 4);

    // 1) QKV projection: M=1536, N=2048, K=512 (tf32-rounded out; q scaled by 0.125*log2e)
    {
        dim3 grid(NL / 128, F3 / 128, NB);
        gemm_tf32_pipe<<<grid, 256>>>(wq, xt, qkv, nullptr, F3, NL, NC, 1);
    }

    // 2) Flash attention (128-query tiles, 16 warps/SM)
    {
        const int smem = (64 * QPAD + 64 * KPAD + 64 * PV_PAD + 128 * PV_PAD)
                         * (int)sizeof(uint32_t);   // 105,472 B
        cudaFuncSetAttribute(attn_tf32,
                             cudaFuncAttributeMaxDynamicSharedMemorySize, smem);
        dim3 grid(NL / 128, NB * HEADS);
        attn_tf32<<<grid, 256, smem>>>(attn);
    }

    // 3) Output projection + bias: M=512, N=2048, K=512
    {
        dim3 grid(NL / 128, HD / 128, NB);
        gemm_tf32_pipe<<<grid, 256>>>(wo, attn, y, b_out, NC, NL, HD, 0);
    }
}